// round 4
// baseline (speedup 1.0000x reference)
#include <cuda_runtime.h>

#define SAMPLES 16
#define THREADS 256

// shared-memory layout (float offsets)
#define SIN_STR 273           // staged-input per-sample stride (row stride 17)
#define CS1     776           // conv1-output per-sample stride (12*64=768 + pad)
#define C2_STR  193           // conv2-output per-sample stride (192 + 1)

enum {
    OFF_C1   = 0,
    SZ_C1    = SAMPLES * CS1,                 // 12416
    OFF_R2   = OFF_C1 + SZ_C1,                // 12416 (input stage, later conv2-out)
    SZ_R2    = SAMPLES * SIN_STR,             // 4368
    OFF_HID  = OFF_R2 + SAMPLES * C2_STR,     // 15504 (fits inside R2 region)
    OFF_W1T  = OFF_R2 + SZ_R2,                // 16784  w1 transposed [25 taps][12 ch]  (16B-aligned rows: 48B)
    OFF_H1B  = OFF_W1T + 304,                 // 17088  [12][8][8]
    OFF_W2T  = OFF_H1B + 768,                 // 17856  [12 c][25 tap][8 fed-outputs]   (32B per tap, 16B-aligned)
    OFF_H2B  = OFF_W2T + 2400,                // 20256  [12][4][4]
    OFF_W3T  = OFF_H2B + 192,                 // 20448  [30 h][192 k] (768B rows, 16B-aligned)
    OFF_H3B  = OFF_W3T + 5760,                // 26208
    OFF_OUTW = OFF_H3B + 32,                  // 26240  [30][10]
    OFF_OUTB = OFF_OUTW + 304,                // 26544
    SMEM_FLOATS = OFF_OUTB + 16               // 26560 floats = 106240 bytes
};

// ---------------- packed f32x2 helpers (FFMA2 path, ptxas won't auto-fuse) ---
typedef unsigned long long ull;

__device__ __forceinline__ ull pk2(float a, float b) {
    ull r;
    asm("mov.b64 %0, {%1, %2};" : "=l"(r) : "f"(a), "f"(b));
    return r;
}
__device__ __forceinline__ void fma2(ull& d, ull a, ull b) {
    asm("fma.rn.f32x2 %0, %1, %2, %0;" : "+l"(d) : "l"(a), "l"(b));
}
__device__ __forceinline__ void unpk2(ull v, float& lo, float& hi) {
    asm("mov.b64 {%0, %1}, %2;" : "=f"(lo), "=f"(hi) : "l"(v));
}

__global__ void __launch_bounds__(THREADS, 2)
modernnet_fused_kernel(const float* __restrict__ x,
                       const float* __restrict__ w1,   // [12,1,5,5]
                       const float* __restrict__ b1,   // [12,8,8]
                       const float* __restrict__ w2,   // [12,8,5,5]
                       const float* __restrict__ b2,   // [12,4,4]
                       const float* __restrict__ w3,   // [192,30]
                       const float* __restrict__ b3,   // [30]
                       const float* __restrict__ wo,   // [30,10]
                       const float* __restrict__ bo,   // [10]
                       float* __restrict__ out,        // [B,10]
                       int nsamp)
{
    extern __shared__ float sm[];
    const int t = threadIdx.x;
    const long base_s = (long)blockIdx.x * SAMPLES;

    // ---------------- Phase A: stage input + weights -------------------------
    for (int i = t; i < SAMPLES * 256; i += THREADS) {
        int s = i >> 8, r = (i >> 4) & 15, c = i & 15;
        long gs = base_s + s;
        float v = (gs < nsamp) ? x[gs * 256 + (i & 255)] : 0.0f;
        sm[OFF_R2 + s * SIN_STR + r * 17 + c] = v;
    }
    // w1 transposed: w1t[k*12 + c] = w1[c*25 + k]
    for (int i = t; i < 300; i += THREADS) {
        int c = i / 25, k = i - c * 25;
        sm[OFF_W1T + k * 12 + c] = w1[i];
    }
    for (int i = t; i < 768; i += THREADS) sm[OFF_H1B + i] = b1[i];
    // w2 transposed: [c][tap][8 slots]; slots 0-3 = group A outs, 4-7 = group B.
    // c 0..3 -> groups {0,2}; 4..7 -> {0,1}; 8..11 -> {1,2}
    for (int i = t; i < 2400; i += THREADS) {
        int c = i / 200, r = i - c * 200;
        int k = r >> 3, u = r & 7;
        int oc, cl;
        if (c < 4)      { oc = (u < 4) ? u       : 8 + (u - 4); cl = c; }
        else if (c < 8) { oc = (u < 4) ? u       : 4 + (u - 4); cl = (u < 4) ? c : c - 4; }
        else            { oc = (u < 4) ? 4 + u   : 8 + (u - 4); cl = c - 4; }
        sm[OFF_W2T + i] = w2[oc * 200 + cl * 25 + k];
    }
    for (int i = t; i < 192; i += THREADS) sm[OFF_H2B + i] = b2[i];
    // w3 transposed: w3t[h*192 + k] = w3[k*30 + h]
    for (int i = t; i < 5760; i += THREADS) {
        int k = i / 30, h = i - k * 30;
        sm[OFF_W3T + h * 192 + k] = w3[i];
    }
    for (int i = t; i < 30;  i += THREADS) sm[OFF_H3B + i]  = b3[i];
    for (int i = t; i < 300; i += THREADS) sm[OFF_OUTW + i] = wo[i];
    for (int i = t; i < 10;  i += THREADS) sm[OFF_OUTB + i] = bo[i];
    __syncthreads();

    // ---------------- Phase B: conv1 (pad=-1, 5x5 s2) + bias + relu ----------
    {
        int sy = t & 127;
        int s  = sy >> 3, y = sy & 7;
        int x0 = (t >> 7) * 4;
        const float* sin_ = &sm[OFF_R2 + s * SIN_STR];
        for (int xx = x0; xx < x0 + 4; ++xx) {
            ull a01 = 0, a23 = 0, a45 = 0, a67 = 0, a89 = 0, aAB = 0;
#pragma unroll
            for (int ky = 0; ky < 5; ky++) {
                int  r   = 2 * y + ky - 2;
                bool rok = (unsigned)r < 16u;
#pragma unroll
                for (int kx = 0; kx < 5; kx++) {
                    int  cc = 2 * xx + kx - 2;
                    bool ok = rok && ((unsigned)cc < 16u);
                    int  ad = ok ? (r * 17 + cc) : 0;
                    float lv = sin_[ad];
                    float v  = ok ? lv : -1.0f;
                    ull  vv  = pk2(v, v);
                    int  k   = ky * 5 + kx;
                    const ulonglong2* w = (const ulonglong2*)&sm[OFF_W1T + k * 12];
                    ulonglong2 p0 = w[0], p1 = w[1], p2 = w[2];
                    fma2(a01, vv, p0.x); fma2(a23, vv, p0.y);
                    fma2(a45, vv, p1.x); fma2(a67, vv, p1.y);
                    fma2(a89, vv, p2.x); fma2(aAB, vv, p2.y);
                }
            }
            float a[12];
            unpk2(a01, a[0], a[1]);  unpk2(a23, a[2],  a[3]);
            unpk2(a45, a[4], a[5]);  unpk2(a67, a[6],  a[7]);
            unpk2(a89, a[8], a[9]);  unpk2(aAB, a[10], a[11]);
            int p = y * 8 + xx;
#pragma unroll
            for (int c = 0; c < 12; c++) {
                float vv = a[c] + sm[OFF_H1B + c * 64 + p];
                sm[OFF_C1 + s * CS1 + c * 64 + p] = vv > 0.0f ? vv : 0.0f;
            }
        }
    }
    __syncthreads();

    // ---------------- Phase C: conv2 (grouped, pad=-1) + bias + relu ---------
    // tap-outer / channel-inner: bounds predicate computed once per tap.
    // acc2 pairs: [0]=outs(0,1) [1]=(2,3) [2]=(4,5) [3]=(6,7) [4]=(8,9) [5]=(10,11)
    // channel c contributes groups: c<4 -> A@0,B@4 ; c<8 -> A@0,B@2 ; else A@2,B@4
    {
        int s = t >> 4, pos = t & 15;
        int ii = pos >> 2, jj = pos & 3;
        const float* c1 = &sm[OFF_C1 + s * CS1];
        ull acc2[6] = {0, 0, 0, 0, 0, 0};

#pragma unroll
        for (int ky = 0; ky < 5; ky++) {
            int  yy  = 2 * ii + ky - 2;
            bool rok = (unsigned)yy < 8u;
#pragma unroll
            for (int kx = 0; kx < 5; kx++) {
                int  xx2 = 2 * jj + kx - 2;
                bool ok  = rok && ((unsigned)xx2 < 8u);
                int  ad  = ok ? (yy * 8 + xx2) : 0;
                int  k   = ky * 5 + kx;
#pragma unroll
                for (int c = 0; c < 12; c++) {
                    float lv = c1[c * 64 + ad];
                    float v  = ok ? lv : -1.0f;
                    ull  vv  = pk2(v, v);
                    const ulonglong2* wt =
                        (const ulonglong2*)&sm[OFF_W2T + c * 200 + k * 8];
                    ulonglong2 qa = wt[0], qb = wt[1];
                    const int ia = (c < 4) ? 0 : (c < 8) ? 0 : 2;
                    const int ib = (c < 4) ? 4 : (c < 8) ? 2 : 4;
                    fma2(acc2[ia],     vv, qa.x); fma2(acc2[ia + 1], vv, qa.y);
                    fma2(acc2[ib],     vv, qb.x); fma2(acc2[ib + 1], vv, qb.y);
                }
            }
        }
        float acc[12];
#pragma unroll
        for (int p2i = 0; p2i < 6; p2i++) unpk2(acc2[p2i], acc[2 * p2i], acc[2 * p2i + 1]);
#pragma unroll
        for (int o = 0; o < 12; o++) {
            float vv = acc[o] + sm[OFF_H2B + o * 16 + pos];
            sm[OFF_R2 + s * C2_STR + o * 16 + pos] = vv > 0.0f ? vv : 0.0f;
        }
    }
    __syncthreads();

    // ---------------- Phase D: fc1 192->30 + relu ----------------------------
    if (t < 240) {
        int h2 = t >> 4, s = t & 15;
        const float* vin = &sm[OFF_R2 + s * C2_STR];
        const ulonglong2* w0  = (const ulonglong2*)&sm[OFF_W3T + (2 * h2 + 0) * 192];
        const ulonglong2* w1v = (const ulonglong2*)&sm[OFF_W3T + (2 * h2 + 1) * 192];
        ull s0p = 0, s1p = 0;
#pragma unroll 8
        for (int k4 = 0; k4 < 48; k4++) {
            ulonglong2 wa = w0[k4], wb = w1v[k4];
            float v0 = vin[4 * k4 + 0], v1 = vin[4 * k4 + 1];
            float v2 = vin[4 * k4 + 2], v3 = vin[4 * k4 + 3];
            ull v01 = pk2(v0, v1), v23 = pk2(v2, v3);
            fma2(s0p, v01, wa.x); fma2(s0p, v23, wa.y);
            fma2(s1p, v01, wb.x); fma2(s1p, v23, wb.y);
        }
        float l0, h0, l1, h1;
        unpk2(s0p, l0, h0);
        unpk2(s1p, l1, h1);
        float s0 = l0 + h0 + sm[OFF_H3B + 2 * h2 + 0];
        float s1 = l1 + h1 + sm[OFF_H3B + 2 * h2 + 1];
        sm[OFF_HID + s * 32 + 2 * h2 + 0] = s0 > 0.0f ? s0 : 0.0f;
        sm[OFF_HID + s * 32 + 2 * h2 + 1] = s1 > 0.0f ? s1 : 0.0f;
    }
    __syncthreads();

    // ---------------- Phase E: fc2 30->10, write output ----------------------
    if (t < 160) {
        int s = t / 10, o = t - s * 10;
        float sum = sm[OFF_OUTB + o];
        const float* hid = &sm[OFF_HID + s * 32];
#pragma unroll
        for (int h = 0; h < 30; h++)
            sum += hid[h] * sm[OFF_OUTW + h * 10 + o];
        long gs = base_s + s;
        if (gs < nsamp) out[gs * 10 + o] = sum;
    }
}

extern "C" void kernel_launch(void* const* d_in, const int* in_sizes, int n_in,
                              void* d_out, int out_size)
{
    const float* x  = (const float*)d_in[0];
    const float* w1 = (const float*)d_in[1];
    const float* b1 = (const float*)d_in[2];
    const float* w2 = (const float*)d_in[3];
    const float* b2 = (const float*)d_in[4];
    const float* w3 = (const float*)d_in[5];
    const float* b3 = (const float*)d_in[6];
    const float* wo = (const float*)d_in[7];
    const float* bo = (const float*)d_in[8];
    float* out = (float*)d_out;

    int nsamp = in_sizes[0] / 256;                       // 131072
    int grid  = (nsamp + SAMPLES - 1) / SAMPLES;         // 8192
    size_t smem = SMEM_FLOATS * sizeof(float);           // 106240 B

    cudaFuncSetAttribute(modernnet_fused_kernel,
                         cudaFuncAttributeMaxDynamicSharedMemorySize, (int)smem);
    modernnet_fused_kernel<<<grid, THREADS, smem>>>(x, w1, b1, w2, b2, w3, b3,
                                                    wo, bo, out, nsamp);
}

// round 6
// speedup vs baseline: 1.2946x; 1.2946x over previous
#include <cuda_runtime.h>

#define SAMPLES 32
#define THREADS 256

#define SIN_STR 324    // staged input per-sample stride: 16 rows x 20 cols (+4 pad)
#define C1STR   808    // conv1-out per-sample stride: [y][8 xx][12 ch] rows of 100 (+8 pad)
#define O2STR   33     // conv2-out transposed: [192 k][33]

enum {
    OFF_C1   = 0,                          // 32 * 808 = 25856
    OFF_R2   = 32 * C1STR,                 // 25856: input stage (32*324=10368), later out2t
    OFF_HID  = OFF_R2 + 192 * O2STR,       // 32192 (+1024 = 33216 <= 36224, inside stage)
    OFF_W1T  = OFF_R2 + 32 * SIN_STR,      // 36224: w1 [25 tap][12 ch]
    OFF_B1T  = OFF_W1T + 304,              // 36528: b1 pairs [6 j][8 xx][8 y][2]
    OFF_W2T  = OFF_B1T + 768,              // 37296: w2 [25 tap][12 o][8 j]
    OFF_H2B  = OFF_W2T + 2400,             // 39696: [12][16]
    OFF_W3T  = OFF_H2B + 192,              // 39888: w3 [30 h][192 k]
    OFF_H3B  = OFF_W3T + 5760,             // 45648
    OFF_OUTW = OFF_H3B + 32,               // 45680: [30][10]
    OFF_OUTB = OFF_OUTW + 304,             // 45984
    OFF_NEG  = OFF_OUTB + 16,              // 46000: 20 floats of -1 (shared pad row)
    SMEM_FLOATS = OFF_NEG + 20             // 46020 floats = 184080 B
};

typedef unsigned long long ull;

__device__ __forceinline__ ull pk2(float a, float b) {
    ull r; asm("mov.b64 %0, {%1, %2};" : "=l"(r) : "f"(a), "f"(b)); return r;
}
__device__ __forceinline__ void fma2(ull& d, ull a, ull b) {
    asm("fma.rn.f32x2 %0, %1, %2, %0;" : "+l"(d) : "l"(a), "l"(b));
}
__device__ __forceinline__ void unpk2(ull v, float& lo, float& hi) {
    asm("mov.b64 {%0, %1}, %2;" : "=f"(lo), "=f"(hi) : "l"(v));
}

__global__ void __launch_bounds__(THREADS, 1)
modernnet_fused_kernel(const float* __restrict__ x,
                       const float* __restrict__ w1,   // [12,1,5,5]
                       const float* __restrict__ b1,   // [12,8,8]
                       const float* __restrict__ w2,   // [12,8,5,5]
                       const float* __restrict__ b2,   // [12,4,4]
                       const float* __restrict__ w3,   // [192,30]
                       const float* __restrict__ b3,   // [30]
                       const float* __restrict__ wo,   // [30,10]
                       const float* __restrict__ bo,   // [10]
                       float* __restrict__ out,        // [B,10]
                       int nsamp)
{
    extern __shared__ float sm[];
    const int t = threadIdx.x;
    const long base_s = (long)blockIdx.x * SAMPLES;

    // ---------------- Phase A: stage input (with -1 halo) + weights ----------
    for (int i = t; i < SAMPLES * 320; i += THREADS) {
        int s = i / 320, rem = i - s * 320;
        int r = rem / 20, c20 = rem - r * 20;
        int cc = c20 - 2;                       // halo cols -2..17
        long gs = base_s + s;
        float v = -1.0f;
        if ((unsigned)cc < 16u && gs < nsamp) v = x[gs * 256 + r * 16 + cc];
        sm[OFF_R2 + s * SIN_STR + r * 20 + c20] = v;
    }
    // w1t[k*12 + c] = w1[c*25 + k]
    for (int i = t; i < 300; i += THREADS) {
        int c = i / 25, k = i - c * 25;
        sm[OFF_W1T + k * 12 + c] = w1[i];
    }
    // b1 packed pairs: b1t[((j*8+xx)*8 + y)*2 + lh] = b1[(2j+lh)*64 + y*8+xx]
    for (int i = t; i < 768; i += THREADS) {
        int i2 = i >> 1, lh = i & 1;
        int j = i2 >> 6, rem = i2 & 63, xx = rem >> 3, y = rem & 7;
        sm[OFF_B1T + i] = b1[(2 * j + lh) * 64 + y * 8 + xx];
    }
    // w2t[k*96 + o*8 + j] = w2[o*200 + j*25 + k]  (j = o's 8 inputs, ascending c)
    for (int i = t; i < 2400; i += THREADS) {
        int k = i / 96, rem = i - k * 96, o = rem >> 3, j = rem & 7;
        sm[OFF_W2T + i] = w2[o * 200 + j * 25 + k];
    }
    for (int i = t; i < 192; i += THREADS) sm[OFF_H2B + i] = b2[i];
    // w3t[h*192 + k] = w3[k*30 + h]
    for (int i = t; i < 5760; i += THREADS) {
        int k = i / 30, h = i - k * 30;
        sm[OFF_W3T + h * 192 + k] = w3[i];
    }
    for (int i = t; i < 30;  i += THREADS) sm[OFF_H3B + i]  = b3[i];
    for (int i = t; i < 300; i += THREADS) sm[OFF_OUTW + i] = wo[i];
    for (int i = t; i < 10;  i += THREADS) sm[OFF_OUTB + i] = bo[i];
    if (t < 20) sm[OFF_NEG + t] = -1.0f;
    __syncthreads();

    // ---------------- Phase B: conv1, thread = (sample, row), all 8 cols -----
    {
        int s = t >> 3, y = t & 7;
        const float* sin_ = &sm[OFF_R2 + s * SIN_STR];
        const float* negrow = &sm[OFF_NEG];

        ull A[48];                                  // [xx][6 ch-pairs]
#pragma unroll
        for (int xx = 0; xx < 8; xx++)
#pragma unroll
            for (int j = 0; j < 6; j++)
                A[xx * 6 + j] = *(const ull*)&sm[OFF_B1T + ((j * 8 + xx) * 8 + y) * 2];

        for (int ky = 0; ky < 5; ky++) {
            int r = 2 * y + ky - 2;
            const float4* rowp = (const float4*)
                (((unsigned)r < 16u) ? (sin_ + r * 20) : negrow);
            float v[20];
            float4 l0 = rowp[0], l1 = rowp[1], l2 = rowp[2], l3 = rowp[3], l4 = rowp[4];
            v[0]=l0.x; v[1]=l0.y; v[2]=l0.z; v[3]=l0.w;
            v[4]=l1.x; v[5]=l1.y; v[6]=l1.z; v[7]=l1.w;
            v[8]=l2.x; v[9]=l2.y; v[10]=l2.z; v[11]=l2.w;
            v[12]=l3.x; v[13]=l3.y; v[14]=l3.z; v[15]=l3.w;
            v[16]=l4.x; v[17]=l4.y; v[18]=l4.z; v[19]=l4.w;
#pragma unroll
            for (int kx = 0; kx < 5; kx++) {
                const ulonglong2* wp =
                    (const ulonglong2*)&sm[OFF_W1T + (ky * 5 + kx) * 12];
                ulonglong2 p0 = wp[0], p1 = wp[1], p2 = wp[2];
#pragma unroll
                for (int xx = 0; xx < 8; xx++) {
                    float vs = v[2 * xx + kx];
                    ull vv = pk2(vs, vs);
                    fma2(A[xx*6+0], vv, p0.x); fma2(A[xx*6+1], vv, p0.y);
                    fma2(A[xx*6+2], vv, p1.x); fma2(A[xx*6+3], vv, p1.y);
                    fma2(A[xx*6+4], vv, p2.x); fma2(A[xx*6+5], vv, p2.y);
                }
            }
        }
        // relu + store channel-minor [y][xx][12], 3x STS.128 per column
        float* c1s = &sm[OFF_C1 + s * C1STR];
#pragma unroll
        for (int xx = 0; xx < 8; xx++) {
            float f[12];
#pragma unroll
            for (int j = 0; j < 6; j++) unpk2(A[xx * 6 + j], f[2 * j], f[2 * j + 1]);
#pragma unroll
            for (int c = 0; c < 12; c++) f[c] = f[c] > 0.0f ? f[c] : 0.0f;
            float4* dst = (float4*)&c1s[y * 100 + xx * 12];
            dst[0] = make_float4(f[0], f[1], f[2],  f[3]);
            dst[1] = make_float4(f[4], f[5], f[6],  f[7]);
            dst[2] = make_float4(f[8], f[9], f[10], f[11]);
        }
    }
    __syncthreads();

    // ---------------- Phase C: conv2, thread = (pos, sample-pair) ------------
    {
        int pos = t & 15, sp = t >> 4;
        int ii = pos >> 2, jj = pos & 3;
        const float* c1a = &sm[OFF_C1 + sp * C1STR];
        const float* c1b = &sm[OFF_C1 + (sp + 16) * C1STR];
        const float* negrow = &sm[OFF_NEG];

        ull acA[12], acB[12];
#pragma unroll
        for (int o = 0; o < 12; o++) { acA[o] = 0; acB[o] = 0; }

        for (int ky = 0; ky < 5; ky++) {
            int yy = 2 * ii + ky - 2;
            for (int kx = 0; kx < 5; kx++) {
                int xx2 = 2 * jj + kx - 2;
                bool ok = ((unsigned)yy < 8u) && ((unsigned)xx2 < 8u);
                int ad = yy * 100 + xx2 * 12;
                const ulonglong2* pa = (const ulonglong2*)(ok ? (c1a + ad) : negrow);
                const ulonglong2* pb = (const ulonglong2*)(ok ? (c1b + ad) : negrow);
                ulonglong2 qa0 = pa[0], qa1 = pa[1], qa2 = pa[2];
                ulonglong2 qb0 = pb[0], qb1 = pb[1], qb2 = pb[2];
                ull a0[6] = {qa0.x, qa0.y, qa1.x, qa1.y, qa2.x, qa2.y};
                ull b0[6] = {qb0.x, qb0.y, qb1.x, qb1.y, qb2.x, qb2.y};
                int k = ky * 5 + kx;
#pragma unroll
                for (int o = 0; o < 12; o++) {
                    const int p0 = (o < 8) ? ((o < 4) ? 0 : 2) : 0;
                    const int p1 = (o < 4) ? 2 : 4;
                    const ulonglong2* wp =
                        (const ulonglong2*)&sm[OFF_W2T + k * 96 + o * 8];
                    ulonglong2 wA = wp[0], wB = wp[1];
                    fma2(acA[o], a0[p0],     wA.x);
                    fma2(acA[o], a0[p0 + 1], wA.y);
                    fma2(acA[o], a0[p1],     wB.x);
                    fma2(acA[o], a0[p1 + 1], wB.y);
                    fma2(acB[o], b0[p0],     wA.x);
                    fma2(acB[o], b0[p0 + 1], wA.y);
                    fma2(acB[o], b0[p1],     wB.x);
                    fma2(acB[o], b0[p1 + 1], wB.y);
                }
            }
        }
        // bias + relu + transposed store out2t[k][33 + s]
        float* o2 = &sm[OFF_R2];
#pragma unroll
        for (int o = 0; o < 12; o++) {
            float lo, hi, bias = sm[OFF_H2B + o * 16 + pos];
            unpk2(acA[o], lo, hi);
            float va = lo + hi + bias;
            unpk2(acB[o], lo, hi);
            float vb = lo + hi + bias;
            int kk = (o * 16 + pos) * O2STR;
            o2[kk + sp]      = va > 0.0f ? va : 0.0f;
            o2[kk + sp + 16] = vb > 0.0f ? vb : 0.0f;
        }
    }
    __syncthreads();

    // ---------------- Phase D: fc1 192->30 + relu (2 samples/thread) ---------
    if (t < 240) {
        int h2 = t >> 4, s = t & 15;
        int h0 = 2 * h2, h1 = 2 * h2 + 1;
        const float* o2 = &sm[OFF_R2];
        const ulonglong2* wp0 = (const ulonglong2*)&sm[OFF_W3T + h0 * 192];
        const ulonglong2* wp1 = (const ulonglong2*)&sm[OFF_W3T + h1 * 192];
        ull s00 = 0, s01 = 0, s10 = 0, s11 = 0;   // [h][sample]
#pragma unroll 4
        for (int k4 = 0; k4 < 48; k4++) {
            ulonglong2 wa = wp0[k4], wb = wp1[k4];
            int k = 4 * k4;
            float a0 = o2[(k+0)*O2STR + s],      a1 = o2[(k+1)*O2STR + s];
            float a2 = o2[(k+2)*O2STR + s],      a3 = o2[(k+3)*O2STR + s];
            float c0 = o2[(k+0)*O2STR + s + 16], c1v = o2[(k+1)*O2STR + s + 16];
            float c2 = o2[(k+2)*O2STR + s + 16], c3 = o2[(k+3)*O2STR + s + 16];
            ull va01 = pk2(a0, a1), va23 = pk2(a2, a3);
            ull vb01 = pk2(c0, c1v), vb23 = pk2(c2, c3);
            fma2(s00, va01, wa.x); fma2(s00, va23, wa.y);
            fma2(s01, vb01, wa.x); fma2(s01, vb23, wa.y);
            fma2(s10, va01, wb.x); fma2(s10, va23, wb.y);
            fma2(s11, vb01, wb.x); fma2(s11, vb23, wb.y);
        }
        float lo, hi;
        float bb0 = sm[OFF_H3B + h0], bb1 = sm[OFF_H3B + h1];
        unpk2(s00, lo, hi); float v00 = lo + hi + bb0;
        unpk2(s01, lo, hi); float v01 = lo + hi + bb0;
        unpk2(s10, lo, hi); float v10 = lo + hi + bb1;
        unpk2(s11, lo, hi); float v11 = lo + hi + bb1;
        sm[OFF_HID + s * 32 + h0]        = v00 > 0.0f ? v00 : 0.0f;
        sm[OFF_HID + (s + 16) * 32 + h0] = v01 > 0.0f ? v01 : 0.0f;
        sm[OFF_HID + s * 32 + h1]        = v10 > 0.0f ? v10 : 0.0f;
        sm[OFF_HID + (s + 16) * 32 + h1] = v11 > 0.0f ? v11 : 0.0f;
    }
    __syncthreads();

    // ---------------- Phase E: fc2 30->10 (2 samples/thread) -----------------
    if (t < 160) {
        int s = t / 10, o = t - s * 10;
        float sum0 = sm[OFF_OUTB + o], sum1 = sum0;
        const float* h0 = &sm[OFF_HID + s * 32];
        const float* h1 = &sm[OFF_HID + (s + 16) * 32];
#pragma unroll
        for (int h = 0; h < 30; h++) {
            float w = sm[OFF_OUTW + h * 10 + o];
            sum0 += h0[h] * w;
            sum1 += h1[h] * w;
        }
        long g0 = base_s + s, g1 = base_s + s + 16;
        if (g0 < nsamp) out[g0 * 10 + o] = sum0;
        if (g1 < nsamp) out[g1 * 10 + o] = sum1;
    }
}

extern "C" void kernel_launch(void* const* d_in, const int* in_sizes, int n_in,
                              void* d_out, int out_size)
{
    const float* x  = (const float*)d_in[0];
    const float* w1 = (const float*)d_in[1];
    const float* b1 = (const float*)d_in[2];
    const float* w2 = (const float*)d_in[3];
    const float* b2 = (const float*)d_in[4];
    const float* w3 = (const float*)d_in[5];
    const float* b3 = (const float*)d_in[6];
    const float* wo = (const float*)d_in[7];
    const float* bo = (const float*)d_in[8];
    float* out = (float*)d_out;

    int nsamp = in_sizes[0] / 256;                       // 131072
    int grid  = (nsamp + SAMPLES - 1) / SAMPLES;         // 4096
    size_t smem = SMEM_FLOATS * sizeof(float);           // 184080 B

    cudaFuncSetAttribute(modernnet_fused_kernel,
                         cudaFuncAttributeMaxDynamicSharedMemorySize, (int)smem);
    modernnet_fused_kernel<<<grid, THREADS, smem>>>(x, w1, b1, w2, b2, w3, b3,
                                                    wo, bo, out, nsamp);
}